// round 5
// baseline (speedup 1.0000x reference)
#include <cuda_runtime.h>
#include <math.h>

#define NV 786432
#define KS 5
#define EMAX (8 * NV)
#define SCAN_BLOCKS 192   // NV / 4096

// ---- static device scratch (no allocations allowed) ----
__device__ float g_t1[(size_t)NV * 32];
__device__ float g_t2[(size_t)NV * 32];
__device__ float g_t3[(size_t)NV * 32];
__device__ float g_t4[(size_t)NV * 32];
__device__ float g_h [(size_t)NV * 32];
__device__ int   g_deg[NV];          // zero at entry: zero-init at load, re-zeroed by finalize
__device__ int   g_excl[NV];
__device__ int   g_rowptr[NV + 1];
__device__ int   g_pos[NV];
__device__ int   g_bsum[SCAN_BLOCKS];
__device__ int2  g_edge[EMAX];       // (col, float_as_int(val)) interleaved

// ===========================================================================
// CSR build (4 kernels)
// ===========================================================================
__global__ void hist_kernel(const int* __restrict__ rows, int* __restrict__ deg, int nedges) {
    int e = blockIdx.x * blockDim.x + threadIdx.x;
    if (e < nedges) atomicAdd(deg + __ldg(rows + e), 1);
}

// 192 blocks x 1024 threads x 4 elems: per-block exclusive scan + block totals
__global__ void scan_local_kernel(const int* __restrict__ deg, int* __restrict__ excl,
                                  int* __restrict__ bsum) {
    __shared__ int warp_sums[32];
    int t = threadIdx.x;
    int base = blockIdx.x * 4096 + t * 4;
    int4 d = *(const int4*)(deg + base);
    int tsum = d.x + d.y + d.z + d.w;
    int lane = t & 31, wid = t >> 5;
    int v = tsum;
#pragma unroll
    for (int o = 1; o < 32; o <<= 1) {
        int n = __shfl_up_sync(~0u, v, o);
        if (lane >= o) v += n;
    }
    if (lane == 31) warp_sums[wid] = v;
    __syncthreads();
    if (wid == 0) {
        int ws = warp_sums[lane];
#pragma unroll
        for (int o = 1; o < 32; o <<= 1) {
            int n = __shfl_up_sync(~0u, ws, o);
            if (lane >= o) ws += n;
        }
        warp_sums[lane] = ws;
    }
    __syncthreads();
    int warp_off = (wid == 0) ? 0 : warp_sums[wid - 1];
    int e0 = warp_off + v - tsum;
    excl[base + 0] = e0;
    excl[base + 1] = e0 + d.x;
    excl[base + 2] = e0 + d.x + d.y;
    excl[base + 3] = e0 + d.x + d.y + d.z;
    if (t == 0) bsum[blockIdx.x] = warp_sums[31];
}

// Every block redundantly scans the 192 block sums (cheap), then finalizes its
// slice of rowptr/pos and zeroes deg for the next replay.
__global__ void finalize_kernel(const int* __restrict__ excl, const int* __restrict__ bsum,
                                int* __restrict__ rowptr, int* __restrict__ pos,
                                int* __restrict__ deg, int nedges) {
    __shared__ int s[256];
    int t = threadIdx.x;
    s[t] = (t < SCAN_BLOCKS) ? bsum[t] : 0;
    __syncthreads();
#pragma unroll
    for (int o = 1; o < 256; o <<= 1) {
        int add = (t >= o) ? s[t - o] : 0;
        __syncthreads();
        s[t] += add;
        __syncthreads();
    }
    int i = blockIdx.x * 256 + t;
    if (i < NV) {
        int sb = i >> 12;                       // 4096 elems per scan block
        int off = (sb == 0) ? 0 : s[sb - 1];
        int r = excl[i] + off;
        rowptr[i] = r;
        pos[i] = r;
        deg[i] = 0;                             // ready for next replay
        if (i == 0) rowptr[NV] = nedges;
    }
}

__global__ void fill_kernel(const int* __restrict__ rows, const int* __restrict__ cols,
                            const float* __restrict__ vals, int* __restrict__ pos,
                            int2* __restrict__ edge, int nedges) {
    int e = blockIdx.x * blockDim.x + threadIdx.x;
    if (e >= nedges) return;
    int r = __ldg(rows + e);
    int p = atomicAdd(pos + r, 1);
    edge[p] = make_int2(__ldg(cols + e), __float_as_int(__ldg(vals + e)));
}

// ===========================================================================
// Gather SpMM with fused Chebyshev recurrence:
//   t[v,:] = scale * sum_j val_j * z[col_j,:]  -  (prev ? prev[v,:] : 0)
// FIN lanes per row (F32: warp-per-row -> zero intra-warp imbalance).
// Edge loop unrolled x4: 8 independent loads in flight per lane.
// ===========================================================================
template<int FIN>
__global__ void spmm_kernel(const int* __restrict__ rowptr, const int2* __restrict__ edge,
                            const float* __restrict__ z, const float* __restrict__ prev,
                            float scale, float* __restrict__ t) {
    int gt = blockIdx.x * blockDim.x + threadIdx.x;
    int v = gt / FIN;
    int f = gt % FIN;
    if (v >= NV) return;
    int j = __ldg(rowptr + v), jend = __ldg(rowptr + v + 1);
    float acc = 0.0f;
    for (; j + 4 <= jend; j += 4) {
        int2 e0 = __ldg(edge + j);
        int2 e1 = __ldg(edge + j + 1);
        int2 e2 = __ldg(edge + j + 2);
        int2 e3 = __ldg(edge + j + 3);
        float z0 = __ldg(z + (size_t)e0.x * FIN + f);
        float z1 = __ldg(z + (size_t)e1.x * FIN + f);
        float z2 = __ldg(z + (size_t)e2.x * FIN + f);
        float z3 = __ldg(z + (size_t)e3.x * FIN + f);
        acc += __int_as_float(e0.y) * z0 + __int_as_float(e1.y) * z1
             + __int_as_float(e2.y) * z2 + __int_as_float(e3.y) * z3;
    }
    for (; j < jend; j++) {
        int2 e = __ldg(edge + j);
        acc += __int_as_float(e.y) * __ldg(z + (size_t)e.x * FIN + f);
    }
    acc *= scale;
    if (prev) acc -= __ldg(prev + (size_t)v * FIN + f);
    t[(size_t)v * FIN + f] = acc;
}

// ===========================================================================
// Fused 5-term GEMM + bias + ELU (+ optional factor-4 max pool).
// 256 threads = 8 warps; each warp processes 32 consecutive vertices (lane=o).
// Block covers 256 vertices -> W smem load amortized 64x vs before.
// ===========================================================================
template<int FIN, bool DOPOOL>
__global__ void gemm5_kernel(const float* __restrict__ t0, const float* __restrict__ t1,
                             const float* __restrict__ t2, const float* __restrict__ t3,
                             const float* __restrict__ t4,
                             const float* __restrict__ W, const float* __restrict__ bias,
                             float* __restrict__ out, float* __restrict__ pooled) {
    __shared__ float Wsh[KS * FIN * 32];
    __shared__ float bsh[32];
    int tid = threadIdx.x;
    for (int i = tid; i < KS * FIN * 32; i += 256) {
        int fk = i >> 5, o = i & 31;
        int f = fk / KS, k = fk % KS;
        Wsh[(k * FIN + f) * 32 + o] = W[i];
    }
    if (tid < 32) bsh[tid] = bias[tid];
    __syncthreads();

    int warp = tid >> 5, o = tid & 31;
    int vbase = blockIdx.x * 256 + warp * 32;
    const float* ts[KS] = {t0, t1, t2, t3, t4};
    float pmax = 0.0f;

    for (int vi = 0; vi < 32; vi++) {
        int v = vbase + vi;
        float acc = bsh[o];
#pragma unroll
        for (int k = 0; k < KS; k++) {
            const float4* tr4 = (const float4*)(ts[k] + (size_t)v * FIN);
            const float* wk = Wsh + k * FIN * 32 + o;
#pragma unroll
            for (int f4 = 0; f4 < FIN / 4; f4++) {
                float4 tv = __ldg(tr4 + f4);
                acc += tv.x * wk[(f4 * 4 + 0) * 32] + tv.y * wk[(f4 * 4 + 1) * 32]
                     + tv.z * wk[(f4 * 4 + 2) * 32] + tv.w * wk[(f4 * 4 + 3) * 32];
            }
        }
        acc = acc > 0.0f ? acc : expm1f(acc);
        out[(size_t)v * 32 + o] = acc;
        if (DOPOOL) {
            pmax = (vi & 3) ? fmaxf(pmax, acc) : acc;
            if ((vi & 3) == 3) pooled[(size_t)(v >> 2) * 32 + o] = pmax;
        }
    }
}

// ===========================================================================
// Host-side layer driver
// ===========================================================================
template<int FIN, bool DOPOOL>
static void run_layer(const float* xin, const float* W, const float* bias,
                      float* out, float* pooled,
                      float* t1, float* t2, float* t3, float* t4,
                      const int* rowptr, const int2* edge) {
    const int TPB = 256;
    const int spmm_blocks = (NV * FIN + TPB - 1) / TPB;

    spmm_kernel<FIN><<<spmm_blocks, TPB>>>(rowptr, edge, xin, nullptr, 1.0f, t1);
    spmm_kernel<FIN><<<spmm_blocks, TPB>>>(rowptr, edge, t1,  xin,     2.0f, t2);
    spmm_kernel<FIN><<<spmm_blocks, TPB>>>(rowptr, edge, t2,  t1,      2.0f, t3);
    spmm_kernel<FIN><<<spmm_blocks, TPB>>>(rowptr, edge, t3,  t2,      2.0f, t4);

    gemm5_kernel<FIN, DOPOOL><<<NV / 256, 256>>>(xin, t1, t2, t3, t4, W, bias, out, pooled);
}

extern "C" void kernel_launch(void* const* d_in, const int* in_sizes, int n_in,
                              void* d_out, int out_size) {
    const float* x    = (const float*)d_in[0];
    const int*   rows = (const int*)  d_in[1];
    const int*   cols = (const int*)  d_in[2];
    const float* vals = (const float*)d_in[3];
    const float* w1   = (const float*)d_in[4];
    const float* b1   = (const float*)d_in[5];
    const float* w2   = (const float*)d_in[6];
    const float* b2   = (const float*)d_in[7];
    int nedges = in_sizes[1];

    float* skip   = (float*)d_out;              // [NV, 32]
    float* pooled = skip + (size_t)NV * 32;     // [NV/4, 32]

    float *t1, *t2, *t3, *t4, *h;
    int *deg, *excl, *rowptr, *pos, *bsum;
    int2* edge;
    cudaGetSymbolAddress((void**)&t1, g_t1);
    cudaGetSymbolAddress((void**)&t2, g_t2);
    cudaGetSymbolAddress((void**)&t3, g_t3);
    cudaGetSymbolAddress((void**)&t4, g_t4);
    cudaGetSymbolAddress((void**)&h,  g_h);
    cudaGetSymbolAddress((void**)&deg,    g_deg);
    cudaGetSymbolAddress((void**)&excl,   g_excl);
    cudaGetSymbolAddress((void**)&rowptr, g_rowptr);
    cudaGetSymbolAddress((void**)&pos,    g_pos);
    cudaGetSymbolAddress((void**)&bsum,   g_bsum);
    cudaGetSymbolAddress((void**)&edge,   g_edge);

    const int TPB = 256;
    const int eblocks = (nedges + TPB - 1) / TPB;

    // ---- CSR build (deg is zero at entry; finalize re-zeroes it) ----
    hist_kernel<<<eblocks, TPB>>>(rows, deg, nedges);
    scan_local_kernel<<<SCAN_BLOCKS, 1024>>>(deg, excl, bsum);
    finalize_kernel<<<(NV + 255) / 256, 256>>>(excl, bsum, rowptr, pos, deg, nedges);
    fill_kernel<<<eblocks, TPB>>>(rows, cols, vals, pos, edge, nedges);

    // ---- Layer 1: ChebConv(16 -> 32) + ELU -> h ----
    run_layer<16, false>(x, w1, b1, h, nullptr, t1, t2, t3, t4, rowptr, edge);

    // ---- Layer 2: ChebConv(32 -> 32) + ELU -> skip, fused pool -> pooled ----
    run_layer<32, true>(h, w2, b2, skip, pooled, t1, t2, t3, t4, rowptr, edge);
}

// round 6
// speedup vs baseline: 1.4774x; 1.4774x over previous
#include <cuda_runtime.h>
#include <math.h>

#define NV 786432
#define KS 5
#define EMAX (8 * NV)
#define SCAN_BLOCKS 192   // NV / 4096

// ---- static device scratch (no allocations allowed) ----
__device__ float g_t1[(size_t)NV * 32];
__device__ float g_t2[(size_t)NV * 32];
__device__ float g_t3[(size_t)NV * 32];
__device__ float g_t4[(size_t)NV * 32];
__device__ float g_h [(size_t)NV * 32];
__device__ int   g_deg[NV];          // zero at entry; finalize re-zeroes for next replay
__device__ int   g_excl[NV];
__device__ int   g_rowptr[NV + 1];
__device__ int   g_pos[NV];
__device__ int   g_bsum[SCAN_BLOCKS];
__device__ int2  g_edge[EMAX];       // (col, float_as_int(val)) interleaved

// ===========================================================================
// CSR build (4 kernels)
// ===========================================================================
__global__ void hist_kernel(const int* __restrict__ rows, int* __restrict__ deg, int nedges) {
    int e = blockIdx.x * blockDim.x + threadIdx.x;
    if (e < nedges) atomicAdd(deg + __ldg(rows + e), 1);
}

// 192 blocks x 1024 threads x 4 elems: per-block exclusive scan + block totals
__global__ void scan_local_kernel(const int* __restrict__ deg, int* __restrict__ excl,
                                  int* __restrict__ bsum) {
    __shared__ int warp_sums[32];
    int t = threadIdx.x;
    int base = blockIdx.x * 4096 + t * 4;
    int4 d = *(const int4*)(deg + base);
    int tsum = d.x + d.y + d.z + d.w;
    int lane = t & 31, wid = t >> 5;
    int v = tsum;
#pragma unroll
    for (int o = 1; o < 32; o <<= 1) {
        int n = __shfl_up_sync(~0u, v, o);
        if (lane >= o) v += n;
    }
    if (lane == 31) warp_sums[wid] = v;
    __syncthreads();
    if (wid == 0) {
        int ws = warp_sums[lane];
#pragma unroll
        for (int o = 1; o < 32; o <<= 1) {
            int n = __shfl_up_sync(~0u, ws, o);
            if (lane >= o) ws += n;
        }
        warp_sums[lane] = ws;
    }
    __syncthreads();
    int warp_off = (wid == 0) ? 0 : warp_sums[wid - 1];
    int e0 = warp_off + v - tsum;
    excl[base + 0] = e0;
    excl[base + 1] = e0 + d.x;
    excl[base + 2] = e0 + d.x + d.y;
    excl[base + 3] = e0 + d.x + d.y + d.z;
    if (t == 0) bsum[blockIdx.x] = warp_sums[31];
}

// Every block redundantly scans the 192 block sums, finalizes its slice of
// rowptr/pos, and zeroes deg for the next replay.
__global__ void finalize_kernel(const int* __restrict__ excl, const int* __restrict__ bsum,
                                int* __restrict__ rowptr, int* __restrict__ pos,
                                int* __restrict__ deg, int nedges) {
    __shared__ int s[256];
    int t = threadIdx.x;
    s[t] = (t < SCAN_BLOCKS) ? bsum[t] : 0;
    __syncthreads();
#pragma unroll
    for (int o = 1; o < 256; o <<= 1) {
        int add = (t >= o) ? s[t - o] : 0;
        __syncthreads();
        s[t] += add;
        __syncthreads();
    }
    int i = blockIdx.x * 256 + t;
    if (i < NV) {
        int sb = i >> 12;
        int off = (sb == 0) ? 0 : s[sb - 1];
        int r = excl[i] + off;
        rowptr[i] = r;
        pos[i] = r;
        deg[i] = 0;
        if (i == 0) rowptr[NV] = nedges;
    }
}

__global__ void fill_kernel(const int* __restrict__ rows, const int* __restrict__ cols,
                            const float* __restrict__ vals, int* __restrict__ pos,
                            int2* __restrict__ edge, int nedges) {
    int e = blockIdx.x * blockDim.x + threadIdx.x;
    if (e >= nedges) return;
    int r = __ldg(rows + e);
    int p = atomicAdd(pos + r, 1);
    edge[p] = make_int2(__ldg(cols + e), __float_as_int(__ldg(vals + e)));
}

// ===========================================================================
// Gather SpMM with fused Chebyshev recurrence:
//   t[v,:] = scale * sum_j val_j * z[col_j,:]  -  (prev ? prev[v,:] : 0)
// LPR = FIN/4 lanes per row; each lane owns one float4 slice.
// Edge loop: 8-wide head (16 loads in flight), then 4-wide, then scalar.
// ===========================================================================
template<int FIN>
__global__ void __launch_bounds__(256) spmm_kernel(
        const int* __restrict__ rowptr, const int2* __restrict__ edge,
        const float* __restrict__ z, const float* __restrict__ prev,
        float scale, float* __restrict__ t) {
    constexpr int LPR = FIN / 4;
    int tid = blockIdx.x * blockDim.x + threadIdx.x;
    int v  = tid / LPR;
    int f4 = tid % LPR;
    if (v >= NV) return;
    int j = __ldg(rowptr + v), jend = __ldg(rowptr + v + 1);
    const float4* z4 = (const float4*)z;
    float4 acc = make_float4(0.f, 0.f, 0.f, 0.f);

    for (; j + 8 <= jend; j += 8) {
        int2 e[8];
        float4 zz[8];
#pragma unroll
        for (int u = 0; u < 8; u++) e[u] = __ldg(edge + j + u);
#pragma unroll
        for (int u = 0; u < 8; u++) zz[u] = __ldg(z4 + (size_t)e[u].x * LPR + f4);
#pragma unroll
        for (int u = 0; u < 8; u++) {
            float w = __int_as_float(e[u].y);
            acc.x += w * zz[u].x; acc.y += w * zz[u].y;
            acc.z += w * zz[u].z; acc.w += w * zz[u].w;
        }
    }
    for (; j + 4 <= jend; j += 4) {
        int2 e[4];
        float4 zz[4];
#pragma unroll
        for (int u = 0; u < 4; u++) e[u] = __ldg(edge + j + u);
#pragma unroll
        for (int u = 0; u < 4; u++) zz[u] = __ldg(z4 + (size_t)e[u].x * LPR + f4);
#pragma unroll
        for (int u = 0; u < 4; u++) {
            float w = __int_as_float(e[u].y);
            acc.x += w * zz[u].x; acc.y += w * zz[u].y;
            acc.z += w * zz[u].z; acc.w += w * zz[u].w;
        }
    }
    for (; j < jend; j++) {
        int2 e = __ldg(edge + j);
        float4 zv = __ldg(z4 + (size_t)e.x * LPR + f4);
        float w = __int_as_float(e.y);
        acc.x += w * zv.x; acc.y += w * zv.y; acc.z += w * zv.z; acc.w += w * zv.w;
    }

    acc.x *= scale; acc.y *= scale; acc.z *= scale; acc.w *= scale;
    if (prev) {
        float4 p = __ldg((const float4*)prev + (size_t)v * LPR + f4);
        acc.x -= p.x; acc.y -= p.y; acc.z -= p.z; acc.w -= p.w;
    }
    ((float4*)t)[(size_t)v * LPR + f4] = acc;
}

// ===========================================================================
// Fused 5-term GEMM + bias + ELU (+ optional factor-4 max pool).
// 256 threads = 8 warps; each warp processes 32 consecutive vertices (lane=o).
// Block covers 256 vertices -> W smem load amortized 64x.
// ===========================================================================
template<int FIN, bool DOPOOL>
__global__ void gemm5_kernel(const float* __restrict__ t0, const float* __restrict__ t1,
                             const float* __restrict__ t2, const float* __restrict__ t3,
                             const float* __restrict__ t4,
                             const float* __restrict__ W, const float* __restrict__ bias,
                             float* __restrict__ out, float* __restrict__ pooled) {
    __shared__ float Wsh[KS * FIN * 32];
    __shared__ float bsh[32];
    int tid = threadIdx.x;
    for (int i = tid; i < KS * FIN * 32; i += 256) {
        int fk = i >> 5, o = i & 31;
        int f = fk / KS, k = fk % KS;
        Wsh[(k * FIN + f) * 32 + o] = W[i];
    }
    if (tid < 32) bsh[tid] = bias[tid];
    __syncthreads();

    int warp = tid >> 5, o = tid & 31;
    int vbase = blockIdx.x * 256 + warp * 32;
    const float* ts[KS] = {t0, t1, t2, t3, t4};
    float pmax = 0.0f;

    for (int vi = 0; vi < 32; vi++) {
        int v = vbase + vi;
        float acc = bsh[o];
#pragma unroll
        for (int k = 0; k < KS; k++) {
            const float4* tr4 = (const float4*)(ts[k] + (size_t)v * FIN);
            const float* wk = Wsh + k * FIN * 32 + o;
#pragma unroll
            for (int f4 = 0; f4 < FIN / 4; f4++) {
                float4 tv = __ldg(tr4 + f4);
                acc += tv.x * wk[(f4 * 4 + 0) * 32] + tv.y * wk[(f4 * 4 + 1) * 32]
                     + tv.z * wk[(f4 * 4 + 2) * 32] + tv.w * wk[(f4 * 4 + 3) * 32];
            }
        }
        acc = acc > 0.0f ? acc : expm1f(acc);
        out[(size_t)v * 32 + o] = acc;
        if (DOPOOL) {
            pmax = (vi & 3) ? fmaxf(pmax, acc) : acc;
            if ((vi & 3) == 3) pooled[(size_t)(v >> 2) * 32 + o] = pmax;
        }
    }
}

// ===========================================================================
// Host-side layer driver
// ===========================================================================
template<int FIN, bool DOPOOL>
static void run_layer(const float* xin, const float* W, const float* bias,
                      float* out, float* pooled,
                      float* t1, float* t2, float* t3, float* t4,
                      const int* rowptr, const int2* edge) {
    const int TPB = 256;
    const int spmm_threads = NV * (FIN / 4);
    const int spmm_blocks = (spmm_threads + TPB - 1) / TPB;

    spmm_kernel<FIN><<<spmm_blocks, TPB>>>(rowptr, edge, xin, nullptr, 1.0f, t1);
    spmm_kernel<FIN><<<spmm_blocks, TPB>>>(rowptr, edge, t1,  xin,     2.0f, t2);
    spmm_kernel<FIN><<<spmm_blocks, TPB>>>(rowptr, edge, t2,  t1,      2.0f, t3);
    spmm_kernel<FIN><<<spmm_blocks, TPB>>>(rowptr, edge, t3,  t2,      2.0f, t4);

    gemm5_kernel<FIN, DOPOOL><<<NV / 256, 256>>>(xin, t1, t2, t3, t4, W, bias, out, pooled);
}

extern "C" void kernel_launch(void* const* d_in, const int* in_sizes, int n_in,
                              void* d_out, int out_size) {
    const float* x    = (const float*)d_in[0];
    const int*   rows = (const int*)  d_in[1];
    const int*   cols = (const int*)  d_in[2];
    const float* vals = (const float*)d_in[3];
    const float* w1   = (const float*)d_in[4];
    const float* b1   = (const float*)d_in[5];
    const float* w2   = (const float*)d_in[6];
    const float* b2   = (const float*)d_in[7];
    int nedges = in_sizes[1];

    float* skip   = (float*)d_out;              // [NV, 32]
    float* pooled = skip + (size_t)NV * 32;     // [NV/4, 32]

    float *t1, *t2, *t3, *t4, *h;
    int *deg, *excl, *rowptr, *pos, *bsum;
    int2* edge;
    cudaGetSymbolAddress((void**)&t1, g_t1);
    cudaGetSymbolAddress((void**)&t2, g_t2);
    cudaGetSymbolAddress((void**)&t3, g_t3);
    cudaGetSymbolAddress((void**)&t4, g_t4);
    cudaGetSymbolAddress((void**)&h,  g_h);
    cudaGetSymbolAddress((void**)&deg,    g_deg);
    cudaGetSymbolAddress((void**)&excl,   g_excl);
    cudaGetSymbolAddress((void**)&rowptr, g_rowptr);
    cudaGetSymbolAddress((void**)&pos,    g_pos);
    cudaGetSymbolAddress((void**)&bsum,   g_bsum);
    cudaGetSymbolAddress((void**)&edge,   g_edge);

    const int TPB = 256;
    const int eblocks = (nedges + TPB - 1) / TPB;

    // ---- CSR build (deg is zero at entry; finalize re-zeroes it) ----
    hist_kernel<<<eblocks, TPB>>>(rows, deg, nedges);
    scan_local_kernel<<<SCAN_BLOCKS, 1024>>>(deg, excl, bsum);
    finalize_kernel<<<(NV + 255) / 256, 256>>>(excl, bsum, rowptr, pos, deg, nedges);
    fill_kernel<<<eblocks, TPB>>>(rows, cols, vals, pos, edge, nedges);

    // ---- Layer 1: ChebConv(16 -> 32) + ELU -> h ----
    run_layer<16, false>(x, w1, b1, h, nullptr, t1, t2, t3, t4, rowptr, edge);

    // ---- Layer 2: ChebConv(32 -> 32) + ELU -> skip, fused pool -> pooled ----
    run_layer<32, true>(h, w2, b2, skip, pooled, t1, t2, t3, t4, rowptr, edge);
}

// round 7
// speedup vs baseline: 1.4895x; 1.0082x over previous
#include <cuda_runtime.h>
#include <math.h>

#define NV 786432
#define KS 5
#define EMAX (8 * NV)
#define SCAN_BLOCKS 192   // NV / 4096

// ---- static device scratch (no allocations allowed) ----
__device__ float g_t1[(size_t)NV * 32];
__device__ float g_t2[(size_t)NV * 32];
__device__ float g_t3[(size_t)NV * 32];
__device__ float g_t4[(size_t)NV * 32];
__device__ float g_h [(size_t)NV * 32];
__device__ int   g_deg[NV];          // zero at entry; finalize re-zeroes for next replay
__device__ int   g_excl[NV];
__device__ int   g_rowptr[NV + 1];
__device__ int   g_pos[NV];
__device__ int   g_bsum[SCAN_BLOCKS];
__device__ int2  g_edge[EMAX];       // (col, float_as_int(val)) interleaved

// ===========================================================================
// CSR build (4 kernels)
// ===========================================================================
__global__ void hist_kernel(const int* __restrict__ rows, int* __restrict__ deg, int nedges) {
    int e = blockIdx.x * blockDim.x + threadIdx.x;
    if (e < nedges) atomicAdd(deg + __ldg(rows + e), 1);
}

// 192 blocks x 1024 threads x 4 elems: per-block exclusive scan + block totals
__global__ void scan_local_kernel(const int* __restrict__ deg, int* __restrict__ excl,
                                  int* __restrict__ bsum) {
    __shared__ int warp_sums[32];
    int t = threadIdx.x;
    int base = blockIdx.x * 4096 + t * 4;
    int4 d = *(const int4*)(deg + base);
    int tsum = d.x + d.y + d.z + d.w;
    int lane = t & 31, wid = t >> 5;
    int v = tsum;
#pragma unroll
    for (int o = 1; o < 32; o <<= 1) {
        int n = __shfl_up_sync(~0u, v, o);
        if (lane >= o) v += n;
    }
    if (lane == 31) warp_sums[wid] = v;
    __syncthreads();
    if (wid == 0) {
        int ws = warp_sums[lane];
#pragma unroll
        for (int o = 1; o < 32; o <<= 1) {
            int n = __shfl_up_sync(~0u, ws, o);
            if (lane >= o) ws += n;
        }
        warp_sums[lane] = ws;
    }
    __syncthreads();
    int warp_off = (wid == 0) ? 0 : warp_sums[wid - 1];
    int e0 = warp_off + v - tsum;
    excl[base + 0] = e0;
    excl[base + 1] = e0 + d.x;
    excl[base + 2] = e0 + d.x + d.y;
    excl[base + 3] = e0 + d.x + d.y + d.z;
    if (t == 0) bsum[blockIdx.x] = warp_sums[31];
}

// Every block redundantly scans the 192 block sums, finalizes its slice of
// rowptr/pos, and zeroes deg for the next replay.
__global__ void finalize_kernel(const int* __restrict__ excl, const int* __restrict__ bsum,
                                int* __restrict__ rowptr, int* __restrict__ pos,
                                int* __restrict__ deg, int nedges) {
    __shared__ int s[256];
    int t = threadIdx.x;
    s[t] = (t < SCAN_BLOCKS) ? bsum[t] : 0;
    __syncthreads();
#pragma unroll
    for (int o = 1; o < 256; o <<= 1) {
        int add = (t >= o) ? s[t - o] : 0;
        __syncthreads();
        s[t] += add;
        __syncthreads();
    }
    int i = blockIdx.x * 256 + t;
    if (i < NV) {
        int sb = i >> 12;
        int off = (sb == 0) ? 0 : s[sb - 1];
        int r = excl[i] + off;
        rowptr[i] = r;
        pos[i] = r;
        deg[i] = 0;
        if (i == 0) rowptr[NV] = nedges;
    }
}

__global__ void fill_kernel(const int* __restrict__ rows, const int* __restrict__ cols,
                            const float* __restrict__ vals, int* __restrict__ pos,
                            int2* __restrict__ edge, int nedges) {
    int e = blockIdx.x * blockDim.x + threadIdx.x;
    if (e >= nedges) return;
    int r = __ldg(rows + e);
    int p = atomicAdd(pos + r, 1);
    edge[p] = make_int2(__ldg(cols + e), __float_as_int(__ldg(vals + e)));
}

// ===========================================================================
// Gather SpMM with fused Chebyshev recurrence:
//   t[v,:] = scale * sum_j val_j * z[col_j,:]  -  (prev ? prev[v,:] : 0)
// LPR = FIN/4 lanes per row; each lane owns one float4 slice.
// Edge loop: masked 8-wide batches ONLY — out-of-range lanes clamp the edge
// index (broadcast duplicate load) and zero the weight. No serial tail.
// ===========================================================================
template<int FIN>
__global__ void __launch_bounds__(256) spmm_kernel(
        const int* __restrict__ rowptr, const int2* __restrict__ edge,
        const float* __restrict__ z, const float* __restrict__ prev,
        float scale, float* __restrict__ t) {
    constexpr int LPR = FIN / 4;
    int tid = blockIdx.x * blockDim.x + threadIdx.x;
    int v  = tid / LPR;
    int f4 = tid % LPR;
    if (v >= NV) return;
    int j0 = __ldg(rowptr + v), jend = __ldg(rowptr + v + 1);
    const float4* z4 = (const float4*)z;
    float4 acc = make_float4(0.f, 0.f, 0.f, 0.f);

    for (int base = j0; base < jend; base += 8) {
        int2 e[8];
        float4 zz[8];
#pragma unroll
        for (int u = 0; u < 8; u++) {
            int idx = base + u < jend ? base + u : jend - 1;  // clamp: duplicate last edge
            e[u] = __ldg(edge + idx);
        }
#pragma unroll
        for (int u = 0; u < 8; u++)
            zz[u] = __ldg(z4 + (size_t)e[u].x * LPR + f4);
#pragma unroll
        for (int u = 0; u < 8; u++) {
            float w = (base + u < jend) ? __int_as_float(e[u].y) : 0.0f;
            acc.x += w * zz[u].x; acc.y += w * zz[u].y;
            acc.z += w * zz[u].z; acc.w += w * zz[u].w;
        }
    }

    acc.x *= scale; acc.y *= scale; acc.z *= scale; acc.w *= scale;
    if (prev) {
        float4 p = __ldg((const float4*)prev + (size_t)v * LPR + f4);
        acc.x -= p.x; acc.y -= p.y; acc.z -= p.z; acc.w -= p.w;
    }
    ((float4*)t)[(size_t)v * LPR + f4] = acc;
}

// ===========================================================================
// Fused 5-term GEMM + bias + ELU (+ optional factor-4 max pool).
// 256 threads = 8 warps; each warp processes 32 consecutive vertices (lane=o).
// Block covers 256 vertices -> W smem load amortized 64x.
// ===========================================================================
template<int FIN, bool DOPOOL>
__global__ void gemm5_kernel(const float* __restrict__ t0, const float* __restrict__ t1,
                             const float* __restrict__ t2, const float* __restrict__ t3,
                             const float* __restrict__ t4,
                             const float* __restrict__ W, const float* __restrict__ bias,
                             float* __restrict__ out, float* __restrict__ pooled) {
    __shared__ float Wsh[KS * FIN * 32];
    __shared__ float bsh[32];
    int tid = threadIdx.x;
    for (int i = tid; i < KS * FIN * 32; i += 256) {
        int fk = i >> 5, o = i & 31;
        int f = fk / KS, k = fk % KS;
        Wsh[(k * FIN + f) * 32 + o] = W[i];
    }
    if (tid < 32) bsh[tid] = bias[tid];
    __syncthreads();

    int warp = tid >> 5, o = tid & 31;
    int vbase = blockIdx.x * 256 + warp * 32;
    const float* ts[KS] = {t0, t1, t2, t3, t4};
    float pmax = 0.0f;

    for (int vi = 0; vi < 32; vi++) {
        int v = vbase + vi;
        float acc = bsh[o];
#pragma unroll
        for (int k = 0; k < KS; k++) {
            const float4* tr4 = (const float4*)(ts[k] + (size_t)v * FIN);
            const float* wk = Wsh + k * FIN * 32 + o;
#pragma unroll
            for (int f4 = 0; f4 < FIN / 4; f4++) {
                float4 tv = __ldg(tr4 + f4);
                acc += tv.x * wk[(f4 * 4 + 0) * 32] + tv.y * wk[(f4 * 4 + 1) * 32]
                     + tv.z * wk[(f4 * 4 + 2) * 32] + tv.w * wk[(f4 * 4 + 3) * 32];
            }
        }
        acc = acc > 0.0f ? acc : expm1f(acc);
        out[(size_t)v * 32 + o] = acc;
        if (DOPOOL) {
            pmax = (vi & 3) ? fmaxf(pmax, acc) : acc;
            if ((vi & 3) == 3) pooled[(size_t)(v >> 2) * 32 + o] = pmax;
        }
    }
}

// ===========================================================================
// Host-side layer driver
// ===========================================================================
template<int FIN, bool DOPOOL>
static void run_layer(const float* xin, const float* W, const float* bias,
                      float* out, float* pooled,
                      float* t1, float* t2, float* t3, float* t4,
                      const int* rowptr, const int2* edge) {
    const int TPB = 256;
    const int spmm_threads = NV * (FIN / 4);
    const int spmm_blocks = (spmm_threads + TPB - 1) / TPB;

    spmm_kernel<FIN><<<spmm_blocks, TPB>>>(rowptr, edge, xin, nullptr, 1.0f, t1);
    spmm_kernel<FIN><<<spmm_blocks, TPB>>>(rowptr, edge, t1,  xin,     2.0f, t2);
    spmm_kernel<FIN><<<spmm_blocks, TPB>>>(rowptr, edge, t2,  t1,      2.0f, t3);
    spmm_kernel<FIN><<<spmm_blocks, TPB>>>(rowptr, edge, t3,  t2,      2.0f, t4);

    gemm5_kernel<FIN, DOPOOL><<<NV / 256, 256>>>(xin, t1, t2, t3, t4, W, bias, out, pooled);
}

extern "C" void kernel_launch(void* const* d_in, const int* in_sizes, int n_in,
                              void* d_out, int out_size) {
    const float* x    = (const float*)d_in[0];
    const int*   rows = (const int*)  d_in[1];
    const int*   cols = (const int*)  d_in[2];
    const float* vals = (const float*)d_in[3];
    const float* w1   = (const float*)d_in[4];
    const float* b1   = (const float*)d_in[5];
    const float* w2   = (const float*)d_in[6];
    const float* b2   = (const float*)d_in[7];
    int nedges = in_sizes[1];

    float* skip   = (float*)d_out;              // [NV, 32]
    float* pooled = skip + (size_t)NV * 32;     // [NV/4, 32]

    float *t1, *t2, *t3, *t4, *h;
    int *deg, *excl, *rowptr, *pos, *bsum;
    int2* edge;
    cudaGetSymbolAddress((void**)&t1, g_t1);
    cudaGetSymbolAddress((void**)&t2, g_t2);
    cudaGetSymbolAddress((void**)&t3, g_t3);
    cudaGetSymbolAddress((void**)&t4, g_t4);
    cudaGetSymbolAddress((void**)&h,  g_h);
    cudaGetSymbolAddress((void**)&deg,    g_deg);
    cudaGetSymbolAddress((void**)&excl,   g_excl);
    cudaGetSymbolAddress((void**)&rowptr, g_rowptr);
    cudaGetSymbolAddress((void**)&pos,    g_pos);
    cudaGetSymbolAddress((void**)&bsum,   g_bsum);
    cudaGetSymbolAddress((void**)&edge,   g_edge);

    const int TPB = 256;
    const int eblocks = (nedges + TPB - 1) / TPB;

    // ---- CSR build (deg is zero at entry; finalize re-zeroes it) ----
    hist_kernel<<<eblocks, TPB>>>(rows, deg, nedges);
    scan_local_kernel<<<SCAN_BLOCKS, 1024>>>(deg, excl, bsum);
    finalize_kernel<<<(NV + 255) / 256, 256>>>(excl, bsum, rowptr, pos, deg, nedges);
    fill_kernel<<<eblocks, TPB>>>(rows, cols, vals, pos, edge, nedges);

    // ---- Layer 1: ChebConv(16 -> 32) + ELU -> h ----
    run_layer<16, false>(x, w1, b1, h, nullptr, t1, t2, t3, t4, rowptr, edge);

    // ---- Layer 2: ChebConv(32 -> 32) + ELU -> skip, fused pool -> pooled ----
    run_layer<32, true>(h, w2, b2, skip, pooled, t1, t2, t3, t4, rowptr, edge);
}